// round 6
// baseline (speedup 1.0000x reference)
#include <cuda_runtime.h>
#include <math.h>

#define B_ 4
#define N_ 4096
#define D_ 768
#define H_ 12
#define HD_ 64
#define E_ 160
#define NC_ 32
#define NU_ 128
#define CH_ 3072
#define OH_ 768
#define BH_ 48

typedef unsigned long long u64;

__device__ float g_qn[H_ * E_ * HD_];
__device__ float g_logits[(size_t)BH_ * N_ * E_];
__device__ float g_Z[BH_ * E_];
__device__ float g_slots[B_ * E_ * D_];
__device__ float g_hid[B_ * NC_ * CH_];
__device__ float g_hid2[B_ * NU_ * OH_];
__device__ float g_eo[B_ * E_ * D_];

__device__ __forceinline__ void ffma2(u64 &a, u64 x, u64 y) {
    asm("fma.rn.f32x2 %0, %1, %2, %0;" : "+l"(a) : "l"(x), "l"(y));
}
__device__ __forceinline__ float sum2(u64 v) {
    float lo, hi;
    asm("mov.b64 {%0,%1}, %2;" : "=f"(lo), "=f"(hi) : "l"(v));
    return lo + hi;
}
__device__ __forceinline__ float gelu_exact(float v) {
    return 0.5f * v * (1.0f + erff(v * 0.70710678f));
}

__global__ void k_zero() {
    int i = blockIdx.x * 256 + threadIdx.x;
    if (i < B_ * E_ * D_) { g_slots[i] = 0.f; g_eo[i] = 0.f; }
    if (i < BH_ * E_) g_Z[i] = 0.f;
}

// q = l2norm(layernorm(phi*qg+qb)); warp per (h,e)
__global__ void k_prep_q(const float* __restrict__ phi, const float* __restrict__ qg,
                         const float* __restrict__ qb, const float* __restrict__ lw,
                         const float* __restrict__ lb) {
    int gw = (blockIdx.x * blockDim.x + threadIdx.x) >> 5, lane = threadIdx.x & 31;
    if (gw >= H_ * E_) return;
    int h = gw / E_, e = gw % E_, d0 = lane, d1 = lane + 32;
    float t0 = phi[(size_t)e * D_ + h * HD_ + d0] * qg[d0] + qb[d0];
    float t1 = phi[(size_t)e * D_ + h * HD_ + d1] * qg[d1] + qb[d1];
    float s = t0 + t1;
#pragma unroll
    for (int o = 16; o; o >>= 1) s += __shfl_xor_sync(~0u, s, o);
    float m = s * (1.f / 64.f), c0 = t0 - m, c1 = t1 - m, v = c0 * c0 + c1 * c1;
#pragma unroll
    for (int o = 16; o; o >>= 1) v += __shfl_xor_sync(~0u, v, o);
    float inv = rsqrtf(v * (1.f / 64.f) + 1e-5f);
    float y0 = c0 * inv * lw[d0] + lb[d0], y1 = c1 * inv * lw[d1] + lb[d1];
    float ss = y0 * y0 + y1 * y1;
#pragma unroll
    for (int o = 16; o; o >>= 1) ss += __shfl_xor_sync(~0u, ss, o);
    float r = 1.f / (sqrtf(ss) + 1e-6f);
    g_qn[gw * HD_ + d0] = y0 * r;
    g_qn[gw * HD_ + d1] = y1 * r;
}

// logits[bh][n][e] = k.q  (k normalized in smem); also Z += exp(l/s0)
__global__ __launch_bounds__(512) void k_logits(const float* __restrict__ x,
                                                const float* __restrict__ kg,
                                                const float* __restrict__ kb,
                                                const float* __restrict__ s0p) {
    extern __shared__ float sm[];
    float* s_k = sm;                 // [64][66]
    float* s_q = sm + 64 * 66;       // [160][66]
    float* s_inv = s_q + 160 * 66;   // [64]
    int tid = threadIdx.x, n0 = blockIdx.x * 64, bh = blockIdx.y;
    int b = bh / H_, h = bh % H_;
#pragma unroll
    for (int i = 0; i < 8; i++) {
        int idx = tid + 512 * i, t = idx >> 6, d = idx & 63;
        s_k[t * 66 + d] = x[((size_t)(b * N_ + n0 + t)) * D_ + h * HD_ + d] * kg[d] + kb[d];
    }
#pragma unroll
    for (int i = 0; i < 20; i++) {
        int idx = tid + 512 * i, e = idx >> 6, d = idx & 63;
        s_q[e * 66 + d] = g_qn[(h * E_ + e) * HD_ + d];
    }
    __syncthreads();
    if (tid < 64) {
        float ss = 0.f;
#pragma unroll
        for (int d = 0; d < 64; d++) { float v = s_k[tid * 66 + d]; ss += v * v; }
        s_inv[tid] = 1.f / (sqrtf(ss) + 1e-6f);
    }
    __syncthreads();
#pragma unroll
    for (int i = 0; i < 8; i++) {
        int idx = tid + 512 * i, t = idx >> 6, d = idx & 63;
        s_k[t * 66 + d] *= s_inv[t];
    }
    __syncthreads();
    int lane = tid & 31, eg = tid >> 5;   // warp eg handles e = eg+16j
    u64 acc[2][10];
#pragma unroll
    for (int a = 0; a < 2; a++)
#pragma unroll
        for (int j = 0; j < 10; j++) acc[a][j] = 0ull;
    const float* k0p = s_k + lane * 66;
    const float* k1p = s_k + (lane + 32) * 66;
#pragma unroll 4
    for (int dp = 0; dp < 32; dp++) {
        u64 k0 = *(const u64*)(k0p + 2 * dp), k1 = *(const u64*)(k1p + 2 * dp);
#pragma unroll
        for (int j = 0; j < 10; j++) {
            u64 q = *(const u64*)(s_q + (eg + 16 * j) * 66 + 2 * dp);
            ffma2(acc[0][j], k0, q);
            ffma2(acc[1][j], k1, q);
        }
    }
    float inv0 = 1.f / __ldg(s0p);
    float l0[10], l1[10], zs[10];
#pragma unroll
    for (int j = 0; j < 10; j++) {
        l0[j] = sum2(acc[0][j]);
        l1[j] = sum2(acc[1][j]);
        zs[j] = __expf(l0[j] * inv0) + __expf(l1[j] * inv0);
#pragma unroll
        for (int o = 16; o; o >>= 1) zs[j] += __shfl_xor_sync(~0u, zs[j], o);
    }
    if (lane == 0)
#pragma unroll
        for (int j = 0; j < 10; j++) atomicAdd(&g_Z[bh * E_ + eg + 16 * j], zs[j]);
    __syncthreads();                      // transpose via smem for coalesced store
    float* s_o = sm;                      // [64][161]
#pragma unroll
    for (int j = 0; j < 10; j++) {
        s_o[lane * 161 + eg + 16 * j] = l0[j];
        s_o[(lane + 32) * 161 + eg + 16 * j] = l1[j];
    }
    __syncthreads();
    size_t base = ((size_t)bh * N_ + n0) * E_;
#pragma unroll
    for (int i = 0; i < 20; i++) {
        int idx = tid + 512 * i, t = idx / 160, e = idx - t * 160;
        g_logits[base + idx] = s_o[t * 161 + e];
    }
}

// slots += x * exp(logit/s0); block = (32e tile, bh, nsplit)
__global__ __launch_bounds__(256) void k_slots(const float* __restrict__ x,
                                               const float* __restrict__ s0p) {
    __shared__ float s_p[32 * 34], s_x[64 * 34];
    int tid = threadIdx.x, e0 = blockIdx.x * 32, bh = blockIdx.y, ns = blockIdx.z;
    int b = bh / H_, h = bh % H_;
    float inv0 = 1.f / __ldg(s0p);
    int hq = tid & 15, eg = tid >> 4;
    u64 acc[2][4];
#pragma unroll
    for (int a = 0; a < 2; a++)
#pragma unroll
        for (int c = 0; c < 4; c++) acc[a][c] = 0ull;
    for (int ck = 0; ck < 64; ck++) {
        int nb = ns * 2048 + ck * 32;
        __syncthreads();
#pragma unroll
        for (int i = 0; i < 4; i++) {
            int idx = tid + 256 * i, e = idx & 31, n = idx >> 5;
            s_p[e * 34 + n] = __expf(g_logits[((size_t)bh * N_ + nb + n) * E_ + e0 + e] * inv0);
        }
#pragma unroll
        for (int i = 0; i < 8; i++) {
            int idx = tid + 256 * i, d = idx & 63, n = idx >> 6;
            s_x[d * 34 + n] = x[((size_t)(b * N_ + nb + n)) * D_ + h * HD_ + d];
        }
        __syncthreads();
#pragma unroll
        for (int np = 0; np < 16; np++) {
            u64 p0 = *(const u64*)(s_p + (eg * 2) * 34 + 2 * np);
            u64 p1 = *(const u64*)(s_p + (eg * 2 + 1) * 34 + 2 * np);
#pragma unroll
            for (int c = 0; c < 4; c++) {
                u64 xv = *(const u64*)(s_x + (hq * 4 + c) * 34 + 2 * np);
                ffma2(acc[0][c], p0, xv);
                ffma2(acc[1][c], p1, xv);
            }
        }
    }
#pragma unroll
    for (int ei = 0; ei < 2; ei++)
#pragma unroll
        for (int c = 0; c < 4; c++)
            atomicAdd(&g_slots[((size_t)(b * E_ + e0 + eg * 2 + ei)) * D_ + h * HD_ + hq * 4 + c],
                      sum2(acc[ei][c]));
}

__global__ void k_finalize() {
    int i = blockIdx.x * 256 + threadIdx.x;
    if (i >= B_ * E_ * D_) return;
    int b = i / (E_ * D_), r = i - b * E_ * D_, e = r / D_, d = r - e * D_;
    g_slots[i] /= g_Z[(b * H_ + (d >> 6)) * E_ + e];
}

// expert layer1: hid = gelu(slots @ w1 + b1); weight-streaming GEMV
__global__ __launch_bounds__(256) void k_mlp1(const float* __restrict__ w1,
                                              const float* __restrict__ b1,
                                              int M, int El, int e0, int core) {
    __shared__ float s_in[4 * 768];
    int tid = threadIdx.x, e = blockIdx.x, m = blockIdx.y * 256 + tid;
    for (int idx = tid; idx < 4 * 768; idx += 256) {
        int b = idx / 768, d = idx - b * 768;
        s_in[idx] = g_slots[((size_t)(b * E_ + e0 + e)) * D_ + d];
    }
    __syncthreads();
    float a0 = 0.f, a1 = 0.f, a2 = 0.f, a3 = 0.f;
    const float* wp = w1 + (size_t)e * 768 * M + m;
#pragma unroll 1
    for (int k0 = 0; k0 < 768; k0 += 8) {
        float wv[8];
#pragma unroll
        for (int i = 0; i < 8; i++) wv[i] = wp[(size_t)(k0 + i) * M];
#pragma unroll
        for (int i = 0; i < 8; i++) {
            a0 = fmaf(s_in[k0 + i], wv[i], a0);
            a1 = fmaf(s_in[768 + k0 + i], wv[i], a1);
            a2 = fmaf(s_in[1536 + k0 + i], wv[i], a2);
            a3 = fmaf(s_in[2304 + k0 + i], wv[i], a3);
        }
    }
    float bias = b1[(size_t)e * M + m];
    float* o = core ? g_hid : g_hid2;
    o[((size_t)(0 * El + e)) * M + m] = gelu_exact(a0 + bias);
    o[((size_t)(1 * El + e)) * M + m] = gelu_exact(a1 + bias);
    o[((size_t)(2 * El + e)) * M + m] = gelu_exact(a2 + bias);
    o[((size_t)(3 * El + e)) * M + m] = gelu_exact(a3 + bias);
}

// expert layer2 with K-split + atomics into g_eo
__global__ __launch_bounds__(256) void k_mlp2(const float* __restrict__ w2,
                                              const float* __restrict__ b2,
                                              int K, int El, int e0, int core) {
    __shared__ float s_h[4 * 768];
    int tid = threadIdx.x, e = blockIdx.x, m = blockIdx.y * 256 + tid, ks = blockIdx.z;
    const float* hid = core ? g_hid : g_hid2;
    for (int idx = tid; idx < 4 * 768; idx += 256) {
        int b = idx / 768, d = idx - b * 768;
        s_h[idx] = hid[((size_t)(b * El + e)) * K + ks * 768 + d];
    }
    __syncthreads();
    float bias = (ks == 0) ? b2[(size_t)e * 768 + m] : 0.f;
    float a0 = bias, a1 = bias, a2 = bias, a3 = bias;
    const float* wp = w2 + ((size_t)e * K + ks * 768) * 768 + m;
#pragma unroll 1
    for (int k0 = 0; k0 < 768; k0 += 8) {
        float wv[8];
#pragma unroll
        for (int i = 0; i < 8; i++) wv[i] = wp[(size_t)(k0 + i) * 768];
#pragma unroll
        for (int i = 0; i < 8; i++) {
            a0 = fmaf(s_h[k0 + i], wv[i], a0);
            a1 = fmaf(s_h[768 + k0 + i], wv[i], a1);
            a2 = fmaf(s_h[1536 + k0 + i], wv[i], a2);
            a3 = fmaf(s_h[2304 + k0 + i], wv[i], a3);
        }
    }
    atomicAdd(&g_eo[((size_t)(0 * E_ + e0 + e)) * D_ + m], a0);
    atomicAdd(&g_eo[((size_t)(1 * E_ + e0 + e)) * D_ + m], a1);
    atomicAdd(&g_eo[((size_t)(2 * E_ + e0 + e)) * D_ + m], a2);
    atomicAdd(&g_eo[((size_t)(3 * E_ + e0 + e)) * D_ + m], a3);
}

// fused entmax15 (Newton) + combine GEMM; block = (64 tokens, bh)
__global__ __launch_bounds__(256) void k_combine(float* __restrict__ out,
                                                 const float* __restrict__ s1p) {
    extern __shared__ float sm[];
    float* s_eoT = sm;              // [64 hd][162]
    float* s_w = sm + 64 * 162;     // [64 t][160]
    int tid = threadIdx.x, lane = tid & 31, wid = tid >> 5;
    int n0 = blockIdx.x * 64, bh = blockIdx.y, b = bh / H_, h = bh % H_;
#pragma unroll
    for (int i = 0; i < 40; i++) {
        int idx = tid + 256 * i, e = idx >> 6, hd = idx & 63;
        s_eoT[hd * 162 + e] = g_eo[((size_t)(b * E_ + e)) * D_ + h * HD_ + hd];
    }
    float inv1 = 1.f / __ldg(s1p);
    for (int i = 0; i < 8; i++) {   // warp per token
        int t = wid * 8 + i;
        const float* lp = g_logits + ((size_t)bh * N_ + n0 + t) * E_;
        float v[5];
#pragma unroll
        for (int j = 0; j < 5; j++) v[j] = lp[lane + 32 * j] * inv1;
        float mx = fmaxf(fmaxf(fmaxf(v[0], v[1]), fmaxf(v[2], v[3])), v[4]);
#pragma unroll
        for (int o = 16; o; o >>= 1) mx = fmaxf(mx, __shfl_xor_sync(~0u, mx, o));
#pragma unroll
        for (int j = 0; j < 5; j++) v[j] = (v[j] - mx) * 0.5f;
        float tau = -1.f;           // Newton from left: f convex decreasing
        for (int it = 0; it < 30; it++) {
            float s1 = 0.f, s2 = 0.f;
#pragma unroll
            for (int j = 0; j < 5; j++) {
                float d = fmaxf(v[j] - tau, 0.f);
                s1 += d;
                s2 = fmaf(d, d, s2);
            }
#pragma unroll
            for (int o = 16; o; o >>= 1) {
                s1 += __shfl_xor_sync(~0u, s1, o);
                s2 += __shfl_xor_sync(~0u, s2, o);
            }
            float dt = (s2 - 1.f) / (2.f * s1);
            tau += dt;
            if (dt < 1e-7f) break;
        }
#pragma unroll
        for (int j = 0; j < 5; j++) {
            float d = fmaxf(v[j] - tau, 0.f);
            s_w[t * 160 + lane + 32 * j] = d * d;
        }
    }
    __syncthreads();
    int hq = tid & 15, tq = tid >> 4;   // thread: 4 tokens x 4 hd, K=160 via e-pairs
    u64 acc[4][4];
#pragma unroll
    for (int tt = 0; tt < 4; tt++)
#pragma unroll
        for (int c = 0; c < 4; c++) acc[tt][c] = 0ull;
#pragma unroll 2
    for (int ep = 0; ep < 80; ep++) {
        u64 wv[4], ev[4];
#pragma unroll
        for (int tt = 0; tt < 4; tt++) wv[tt] = *(const u64*)(s_w + (tq * 4 + tt) * 160 + 2 * ep);
#pragma unroll
        for (int c = 0; c < 4; c++) ev[c] = *(const u64*)(s_eoT + (hq * 4 + c) * 162 + 2 * ep);
#pragma unroll
        for (int tt = 0; tt < 4; tt++)
#pragma unroll
            for (int c = 0; c < 4; c++) ffma2(acc[tt][c], wv[tt], ev[c]);
    }
#pragma unroll
    for (int tt = 0; tt < 4; tt++) {
        float4 r = make_float4(sum2(acc[tt][0]), sum2(acc[tt][1]),
                               sum2(acc[tt][2]), sum2(acc[tt][3]));
        *(float4*)(out + ((size_t)(b * N_ + n0 + tq * 4 + tt)) * D_ + h * HD_ + hq * 4) = r;
    }
}

extern "C" void kernel_launch(void* const* d_in, const int* in_sizes, int n_in,
                              void* d_out, int out_size) {
    const float* x   = (const float*)d_in[0];
    const float* phi = (const float*)d_in[1];
    const float* kgm = (const float*)d_in[2];
    const float* kbt = (const float*)d_in[3];
    const float* qgm = (const float*)d_in[4];
    const float* qbt = (const float*)d_in[5];
    const float* lnw = (const float*)d_in[6];
    const float* lnb = (const float*)d_in[7];
    const float* s0  = (const float*)d_in[8];
    const float* s1  = (const float*)d_in[9];
    const float* cw1 = (const float*)d_in[10];
    const float* cb1 = (const float*)d_in[11];
    const float* cw2 = (const float*)d_in[12];
    const float* cb2 = (const float*)d_in[13];
    const float* ow1 = (const float*)d_in[14];
    const float* ob1 = (const float*)d_in[15];
    const float* ow2 = (const float*)d_in[16];
    const float* ob2 = (const float*)d_in[17];
    float* out = (float*)d_out;

    const int SM_LOG = (64 * 66 + 160 * 66 + 64) * 4;
    const int SM_CMB = (64 * 162 + 64 * 160) * 4;
    cudaFuncSetAttribute(k_logits, cudaFuncAttributeMaxDynamicSharedMemorySize, SM_LOG);
    cudaFuncSetAttribute(k_combine, cudaFuncAttributeMaxDynamicSharedMemorySize, SM_CMB);

    k_zero<<<1920, 256>>>();
    k_prep_q<<<60, 1024>>>(phi, qgm, qbt, lnw, lnb);
    k_logits<<<dim3(64, 48), 512, SM_LOG>>>(x, kgm, kbt, s0);
    k_slots<<<dim3(5, 48, 2), 256>>>(x, s0);
    k_finalize<<<1920, 256>>>();
    k_mlp1<<<dim3(NC_, 12), 256>>>(cw1, cb1, CH_, NC_, 0, 1);
    k_mlp1<<<dim3(NU_, 3), 256>>>(ow1, ob1, OH_, NU_, NC_, 0);
    k_mlp2<<<dim3(NC_, 3, 4), 256>>>(cw2, cb2, CH_, NC_, 0, 1);
    k_mlp2<<<dim3(NU_, 3, 1), 256>>>(ow2, ob2, OH_, NU_, NC_, 0);
    k_combine<<<dim3(64, 48), 256, SM_CMB>>>(out, s1);
}

// round 10
// speedup vs baseline: 1.0488x; 1.0488x over previous
#include <cuda_runtime.h>
#include <math.h>

#define B_ 4
#define N_ 4096
#define D_ 768
#define H_ 12
#define HD_ 64
#define E_ 160
#define NC_ 32
#define NU_ 128
#define CH_ 3072
#define OH_ 768
#define BH_ 48

typedef unsigned long long u64;

__device__ float g_qn[H_ * E_ * HD_];
__device__ float g_logits[(size_t)BH_ * N_ * E_];
__device__ float g_Z[BH_ * E_];
__device__ float g_slots[B_ * E_ * D_];
__device__ float g_hid[B_ * NC_ * CH_];
__device__ float g_hid2[B_ * NU_ * OH_];
__device__ float g_eo[B_ * E_ * D_];

__device__ __forceinline__ void ffma2(u64 &a, u64 x, u64 y) {
    asm("fma.rn.f32x2 %0, %1, %2, %0;" : "+l"(a) : "l"(x), "l"(y));
}
__device__ __forceinline__ float sum2(u64 v) {
    float lo, hi;
    asm("mov.b64 {%0,%1}, %2;" : "=f"(lo), "=f"(hi) : "l"(v));
    return lo + hi;
}
__device__ __forceinline__ float gelu_exact(float v) {
    return 0.5f * v * (1.0f + erff(v * 0.70710678f));
}

__global__ void k_zero() {
    int i = blockIdx.x * 256 + threadIdx.x;
    if (i < B_ * E_ * D_) { g_slots[i] = 0.f; g_eo[i] = 0.f; }
    if (i < BH_ * E_) g_Z[i] = 0.f;
}

__global__ void k_prep_q(const float* __restrict__ phi, const float* __restrict__ qg,
                         const float* __restrict__ qb, const float* __restrict__ lw,
                         const float* __restrict__ lb) {
    int gw = (blockIdx.x * blockDim.x + threadIdx.x) >> 5, lane = threadIdx.x & 31;
    if (gw >= H_ * E_) return;
    int h = gw / E_, e = gw % E_, d0 = lane, d1 = lane + 32;
    float t0 = phi[(size_t)e * D_ + h * HD_ + d0] * qg[d0] + qb[d0];
    float t1 = phi[(size_t)e * D_ + h * HD_ + d1] * qg[d1] + qb[d1];
    float s = t0 + t1;
#pragma unroll
    for (int o = 16; o; o >>= 1) s += __shfl_xor_sync(~0u, s, o);
    float m = s * (1.f / 64.f), c0 = t0 - m, c1 = t1 - m, v = c0 * c0 + c1 * c1;
#pragma unroll
    for (int o = 16; o; o >>= 1) v += __shfl_xor_sync(~0u, v, o);
    float inv = rsqrtf(v * (1.f / 64.f) + 1e-5f);
    float y0 = c0 * inv * lw[d0] + lb[d0], y1 = c1 * inv * lw[d1] + lb[d1];
    float ss = y0 * y0 + y1 * y1;
#pragma unroll
    for (int o = 16; o; o >>= 1) ss += __shfl_xor_sync(~0u, ss, o);
    float r = 1.f / (sqrtf(ss) + 1e-6f);
    g_qn[gw * HD_ + d0] = y0 * r;
    g_qn[gw * HD_ + d1] = y1 * r;
}

__global__ __launch_bounds__(512) void k_logits(const float* __restrict__ x,
                                                const float* __restrict__ kg,
                                                const float* __restrict__ kb,
                                                const float* __restrict__ s0p) {
    extern __shared__ float sm[];
    float* s_k = sm;
    float* s_q = sm + 64 * 66;
    float* s_inv = s_q + 160 * 66;
    int tid = threadIdx.x, n0 = blockIdx.x * 64, bh = blockIdx.y;
    int b = bh / H_, h = bh % H_;
#pragma unroll
    for (int i = 0; i < 8; i++) {
        int idx = tid + 512 * i, t = idx >> 6, d = idx & 63;
        s_k[t * 66 + d] = x[((size_t)(b * N_ + n0 + t)) * D_ + h * HD_ + d] * kg[d] + kb[d];
    }
#pragma unroll
    for (int i = 0; i < 20; i++) {
        int idx = tid + 512 * i, e = idx >> 6, d = idx & 63;
        s_q[e * 66 + d] = g_qn[(h * E_ + e) * HD_ + d];
    }
    __syncthreads();
    if (tid < 64) {
        float ss = 0.f;
#pragma unroll
        for (int d = 0; d < 64; d++) { float v = s_k[tid * 66 + d]; ss += v * v; }
        s_inv[tid] = 1.f / (sqrtf(ss) + 1e-6f);
    }
    __syncthreads();
#pragma unroll
    for (int i = 0; i < 8; i++) {
        int idx = tid + 512 * i, t = idx >> 6, d = idx & 63;
        s_k[t * 66 + d] *= s_inv[t];
    }
    __syncthreads();
    int lane = tid & 31, eg = tid >> 5;
    u64 acc[2][10];
#pragma unroll
    for (int a = 0; a < 2; a++)
#pragma unroll
        for (int j = 0; j < 10; j++) acc[a][j] = 0ull;
    const float* k0p = s_k + lane * 66;
    const float* k1p = s_k + (lane + 32) * 66;
#pragma unroll 4
    for (int dp = 0; dp < 32; dp++) {
        u64 k0 = *(const u64*)(k0p + 2 * dp), k1 = *(const u64*)(k1p + 2 * dp);
#pragma unroll
        for (int j = 0; j < 10; j++) {
            u64 q = *(const u64*)(s_q + (eg + 16 * j) * 66 + 2 * dp);
            ffma2(acc[0][j], k0, q);
            ffma2(acc[1][j], k1, q);
        }
    }
    float inv0 = 1.f / __ldg(s0p);
    float l0[10], l1[10], zs[10];
#pragma unroll
    for (int j = 0; j < 10; j++) {
        l0[j] = sum2(acc[0][j]);
        l1[j] = sum2(acc[1][j]);
        zs[j] = __expf(l0[j] * inv0) + __expf(l1[j] * inv0);
#pragma unroll
        for (int o = 16; o; o >>= 1) zs[j] += __shfl_xor_sync(~0u, zs[j], o);
    }
    if (lane == 0)
#pragma unroll
        for (int j = 0; j < 10; j++) atomicAdd(&g_Z[bh * E_ + eg + 16 * j], zs[j]);
    __syncthreads();
    float* s_o = sm;
#pragma unroll
    for (int j = 0; j < 10; j++) {
        s_o[lane * 161 + eg + 16 * j] = l0[j];
        s_o[(lane + 32) * 161 + eg + 16 * j] = l1[j];
    }
    __syncthreads();
    size_t base = ((size_t)bh * N_ + n0) * E_;
#pragma unroll
    for (int i = 0; i < 20; i++) {
        int idx = tid + 512 * i, t = idx / 160, e = idx - t * 160;
        g_logits[base + idx] = s_o[t * 161 + e];
    }
}

// slots: full 160e x 64hd per block, 1024-token chunk; tile 10e x 4hd/thread
__global__ __launch_bounds__(256) void k_slots(const float* __restrict__ x,
                                               const float* __restrict__ s0p) {
    __shared__ float s_p[32 * 162];
    __shared__ float s_x[32 * 68];
    int tid = threadIdx.x, bh = blockIdx.x, nc = blockIdx.y;
    int b = bh / H_, h = bh % H_;
    float inv0 = 1.f / __ldg(s0p);
    int te = tid & 15, th = tid >> 4;
    u64 acc[5][4];
#pragma unroll
    for (int j = 0; j < 5; j++)
#pragma unroll
        for (int c = 0; c < 4; c++) acc[j][c] = 0ull;
    for (int sb = 0; sb < 32; sb++) {
        int nb = nc * 1024 + sb * 32;
        __syncthreads();
#pragma unroll
        for (int i = 0; i < 20; i++) {
            int idx = tid + 256 * i;
            int n = idx / 160, e = idx - n * 160;
            s_p[n * 162 + e] = __expf(g_logits[((size_t)bh * N_ + nb + n) * E_ + e] * inv0);
        }
#pragma unroll
        for (int i = 0; i < 8; i++) {
            int idx = tid + 256 * i, n = idx >> 6, d = idx & 63;
            s_x[n * 68 + d] = x[((size_t)(b * N_ + nb + n)) * D_ + h * HD_ + d];
        }
        __syncthreads();
#pragma unroll 2
        for (int n = 0; n < 32; n++) {
            u64 xd[4];
#pragma unroll
            for (int c = 0; c < 4; c++) {
                float xv = s_x[n * 68 + th * 4 + c];
                asm("mov.b64 %0, {%1,%1};" : "=l"(xd[c]) : "f"(xv));
            }
#pragma unroll
            for (int j = 0; j < 5; j++) {
                u64 pv = *(const u64*)(s_p + n * 162 + te * 10 + 2 * j);
#pragma unroll
                for (int c = 0; c < 4; c++) ffma2(acc[j][c], pv, xd[c]);
            }
        }
    }
#pragma unroll
    for (int j = 0; j < 5; j++)
#pragma unroll
        for (int c = 0; c < 4; c++) {
            float lo, hi;
            asm("mov.b64 {%0,%1}, %2;" : "=f"(lo), "=f"(hi) : "l"(acc[j][c]));
            int e = te * 10 + 2 * j, hd = th * 4 + c;
            atomicAdd(&g_slots[((size_t)(b * E_ + e)) * D_ + h * HD_ + hd], lo);
            atomicAdd(&g_slots[((size_t)(b * E_ + e + 1)) * D_ + h * HD_ + hd], hi);
        }
}

__global__ void k_finalize() {
    int i = blockIdx.x * 256 + threadIdx.x;
    if (i >= B_ * E_ * D_) return;
    int b = i / (E_ * D_), r = i - b * E_ * D_, e = r / D_, d = r - e * D_;
    g_slots[i] /= g_Z[(b * H_ + (d >> 6)) * E_ + e];
}

// MLP layer1: float4 weight streaming, 4 m-cols x 4 batches per thread
__global__ __launch_bounds__(128) void k_mlp1(const float* __restrict__ w1,
                                              const float* __restrict__ b1,
                                              int M, int El, int e0, int core) {
    __shared__ float s_in[4 * 768];
    int tid = threadIdx.x, e = blockIdx.x;
    int m = (blockIdx.y * 128 + tid) * 4;
    for (int idx = tid; idx < 4 * 768; idx += 128) {
        int b = idx / 768, d = idx - b * 768;
        s_in[idx] = g_slots[((size_t)(b * E_ + e0 + e)) * D_ + d];
    }
    __syncthreads();
    if (m >= M) return;
    float a[4][4];
#pragma unroll
    for (int bb = 0; bb < 4; bb++)
#pragma unroll
        for (int c = 0; c < 4; c++) a[bb][c] = 0.f;
    size_t st4 = M >> 2;
    const float4* wp = (const float4*)w1 + (size_t)e * 768 * st4 + (m >> 2);
#pragma unroll 1
    for (int k0 = 0; k0 < 768; k0 += 8) {
        float4 wv[8];
#pragma unroll
        for (int i = 0; i < 8; i++) wv[i] = wp[(size_t)(k0 + i) * st4];
#pragma unroll
        for (int i = 0; i < 8; i++)
#pragma unroll
            for (int bb = 0; bb < 4; bb++) {
                float sv = s_in[bb * 768 + k0 + i];
                a[bb][0] = fmaf(sv, wv[i].x, a[bb][0]);
                a[bb][1] = fmaf(sv, wv[i].y, a[bb][1]);
                a[bb][2] = fmaf(sv, wv[i].z, a[bb][2]);
                a[bb][3] = fmaf(sv, wv[i].w, a[bb][3]);
            }
    }
    float4 bv = *(const float4*)(b1 + (size_t)e * M + m);
    float* o = core ? g_hid : g_hid2;
#pragma unroll
    for (int bb = 0; bb < 4; bb++) {
        float4 r;
        r.x = gelu_exact(a[bb][0] + bv.x);
        r.y = gelu_exact(a[bb][1] + bv.y);
        r.z = gelu_exact(a[bb][2] + bv.z);
        r.w = gelu_exact(a[bb][3] + bv.w);
        *(float4*)(o + ((size_t)(bb * El + e)) * M + m) = r;
    }
}

// MLP layer2: float4 streaming, K-split, atomics into g_eo
__global__ __launch_bounds__(128) void k_mlp2(const float* __restrict__ w2,
                                              const float* __restrict__ b2,
                                              int K, int El, int e0, int core) {
    __shared__ float s_h[4 * 768];
    int tid = threadIdx.x, e = blockIdx.x, ks = blockIdx.z;
    int m = (blockIdx.y * 128 + tid) * 4;
    const float* hid = core ? g_hid : g_hid2;
    for (int idx = tid; idx < 4 * 768; idx += 128) {
        int b = idx / 768, d = idx - b * 768;
        s_h[idx] = hid[((size_t)(b * El + e)) * K + ks * 768 + d];
    }
    __syncthreads();
    if (m >= 768) return;
    float a[4][4];
    float4 bv = make_float4(0.f, 0.f, 0.f, 0.f);
    if (ks == 0) bv = *(const float4*)(b2 + (size_t)e * 768 + m);
#pragma unroll
    for (int bb = 0; bb < 4; bb++) {
        a[bb][0] = bv.x; a[bb][1] = bv.y; a[bb][2] = bv.z; a[bb][3] = bv.w;
    }
    const float4* wp = (const float4*)w2 + ((size_t)e * K + ks * 768) * 192 + (m >> 2);
#pragma unroll 1
    for (int k0 = 0; k0 < 768; k0 += 8) {
        float4 wv[8];
#pragma unroll
        for (int i = 0; i < 8; i++) wv[i] = wp[(size_t)(k0 + i) * 192];
#pragma unroll
        for (int i = 0; i < 8; i++)
#pragma unroll
            for (int bb = 0; bb < 4; bb++) {
                float sv = s_h[bb * 768 + k0 + i];
                a[bb][0] = fmaf(sv, wv[i].x, a[bb][0]);
                a[bb][1] = fmaf(sv, wv[i].y, a[bb][1]);
                a[bb][2] = fmaf(sv, wv[i].z, a[bb][2]);
                a[bb][3] = fmaf(sv, wv[i].w, a[bb][3]);
            }
    }
#pragma unroll
    for (int bb = 0; bb < 4; bb++)
#pragma unroll
        for (int c = 0; c < 4; c++)
            atomicAdd(&g_eo[((size_t)(bb * E_ + e0 + e)) * D_ + m + c], a[bb][c]);
}

__global__ __launch_bounds__(256) void k_combine(float* __restrict__ out,
                                                 const float* __restrict__ s1p) {
    extern __shared__ float sm[];
    float* s_eoT = sm;
    float* s_w = sm + 64 * 162;
    int tid = threadIdx.x, lane = tid & 31, wid = tid >> 5;
    int n0 = blockIdx.x * 64, bh = blockIdx.y, b = bh / H_, h = bh % H_;
#pragma unroll
    for (int i = 0; i < 40; i++) {
        int idx = tid + 256 * i, e = idx >> 6, hd = idx & 63;
        s_eoT[hd * 162 + e] = g_eo[((size_t)(b * E_ + e)) * D_ + h * HD_ + hd];
    }
    float inv1 = 1.f / __ldg(s1p);
    for (int i = 0; i < 8; i++) {
        int t = wid * 8 + i;
        const float* lp = g_logits + ((size_t)bh * N_ + n0 + t) * E_;
        float v[5];
#pragma unroll
        for (int j = 0; j < 5; j++) v[j] = lp[lane + 32 * j] * inv1;
        float mx = fmaxf(fmaxf(fmaxf(v[0], v[1]), fmaxf(v[2], v[3])), v[4]);
#pragma unroll
        for (int o = 16; o; o >>= 1) mx = fmaxf(mx, __shfl_xor_sync(~0u, mx, o));
#pragma unroll
        for (int j = 0; j < 5; j++) v[j] = (v[j] - mx) * 0.5f;
        float tau = -1.f;
        for (int it = 0; it < 30; it++) {
            float s1 = 0.f, s2 = 0.f;
#pragma unroll
            for (int j = 0; j < 5; j++) {
                float d = fmaxf(v[j] - tau, 0.f);
                s1 += d;
                s2 = fmaf(d, d, s2);
            }
#pragma unroll
            for (int o = 16; o; o >>= 1) {
                s1 += __shfl_xor_sync(~0u, s1, o);
                s2 += __shfl_xor_sync(~0u, s2, o);
            }
            float dt = (s2 - 1.f) / (2.f * s1);
            tau += dt;
            if (dt < 1e-7f) break;
        }
#pragma unroll
        for (int j = 0; j < 5; j++) {
            float d = fmaxf(v[j] - tau, 0.f);
            s_w[t * 160 + lane + 32 * j] = d * d;
        }
    }
    __syncthreads();
    int hq = tid & 15, tq = tid >> 4;
    u64 acc[4][4];
#pragma unroll
    for (int tt = 0; tt < 4; tt++)
#pragma unroll
        for (int c = 0; c < 4; c++) acc[tt][c] = 0ull;
#pragma unroll 2
    for (int ep = 0; ep < 80; ep++) {
        u64 wv[4], ev[4];
#pragma unroll
        for (int tt = 0; tt < 4; tt++) wv[tt] = *(const u64*)(s_w + (tq * 4 + tt) * 160 + 2 * ep);
#pragma unroll
        for (int c = 0; c < 4; c++) ev[c] = *(const u64*)(s_eoT + (hq * 4 + c) * 162 + 2 * ep);
#pragma unroll
        for (int tt = 0; tt < 4; tt++)
#pragma unroll
            for (int c = 0; c < 4; c++) ffma2(acc[tt][c], wv[tt], ev[c]);
    }
#pragma unroll
    for (int tt = 0; tt < 4; tt++) {
        float4 r = make_float4(sum2(acc[tt][0]), sum2(acc[tt][1]),
                               sum2(acc[tt][2]), sum2(acc[tt][3]));
        *(float4*)(out + ((size_t)(b * N_ + n0 + tq * 4 + tt)) * D_ + h * HD_ + hq * 4) = r;
    }
}

extern "C" void kernel_launch(void* const* d_in, const int* in_sizes, int n_in,
                              void* d_out, int out_size) {
    const float* x   = (const float*)d_in[0];
    const float* phi = (const float*)d_in[1];
    const float* kgm = (const float*)d_in[2];
    const float* kbt = (const float*)d_in[3];
    const float* qgm = (const float*)d_in[4];
    const float* qbt = (const float*)d_in[5];
    const float* lnw = (const float*)d_in[6];
    const float* lnb = (const float*)d_in[7];
    const float* s0  = (const float*)d_in[8];
    const float* s1  = (const float*)d_in[9];
    const float* cw1 = (const float*)d_in[10];
    const float* cb1 = (const float*)d_in[11];
    const float* cw2 = (const float*)d_in[12];
    const float* cb2 = (const float*)d_in[13];
    const float* ow1 = (const float*)d_in[14];
    const float* ob1 = (const float*)d_in[15];
    const float* ow2 = (const float*)d_in[16];
    const float* ob2 = (const float*)d_in[17];
    float* out = (float*)d_out;

    const int SM_LOG = (64 * 66 + 160 * 66 + 64) * 4;
    const int SM_CMB = (64 * 162 + 64 * 160) * 4;
    cudaFuncSetAttribute(k_logits, cudaFuncAttributeMaxDynamicSharedMemorySize, SM_LOG);
    cudaFuncSetAttribute(k_combine, cudaFuncAttributeMaxDynamicSharedMemorySize, SM_CMB);

    k_zero<<<1920, 256>>>();
    k_prep_q<<<60, 1024>>>(phi, qgm, qbt, lnw, lnb);
    k_logits<<<dim3(64, 48), 512, SM_LOG>>>(x, kgm, kbt, s0);
    k_slots<<<dim3(48, 4), 256>>>(x, s0);
    k_finalize<<<1920, 256>>>();
    k_mlp1<<<dim3(NC_, 6), 128>>>(cw1, cb1, CH_, NC_, 0, 1);
    k_mlp1<<<dim3(NU_, 2), 128>>>(ow1, ob1, OH_, NU_, NC_, 0);
    k_mlp2<<<dim3(NC_, 2, 4), 128>>>(cw2, cb2, CH_, NC_, 0, 1);
    k_mlp2<<<dim3(NU_, 2, 1), 128>>>(ow2, ob2, OH_, NU_, NC_, 0);
    k_combine<<<dim3(64, 48), 256, SM_CMB>>>(out, s1);
}